// round 1
// baseline (speedup 1.0000x reference)
#include <cuda_runtime.h>
#include <cuda_bf16.h>
#include <math.h>

#define Bsz 4
#define Nn 4096
#define DIMc 256
#define Hh 8
#define DHd 64
#define Pp 2
#define INNERc 512
#define MQ (Bsz*Nn)      /* 16384 */
#define MKV (2*Bsz*Nn)   /* 32768 */

// ---------------- scratch (device globals; no allocs allowed) ----------------
__device__ float g_qln[MQ * INNERc];       // LN(cat(x,prev_x)) : 32MB
__device__ float g_q  [MQ * INNERc];       // q projection      : 32MB
__device__ float g_kln[MKV * DIMc];        // LN_k(kv)          : 32MB
__device__ float g_vln[MKV * DIMc];        // LN_v(kv)          : 32MB
__device__ float g_k  [MKV * INNERc];      // k projection      : 64MB
__device__ float g_v  [MKV * INNERc];      // v projection      : 64MB
__device__ float g_off[MQ * (Hh*Pp)];      // offsets (B,N,16)  : 1MB
__device__ float g_ao [MQ * INNERc];       // attention output  : 32MB

// ---------------- block reduce (sum of two values) ----------------
__device__ __forceinline__ float2 blockReduce2(float a, float b) {
    __shared__ float2 sbuf[8];
    #pragma unroll
    for (int o = 16; o > 0; o >>= 1) {
        a += __shfl_xor_sync(0xffffffffu, a, o);
        b += __shfl_xor_sync(0xffffffffu, b, o);
    }
    int w = threadIdx.x >> 5;
    if ((threadIdx.x & 31) == 0) sbuf[w] = make_float2(a, b);
    __syncthreads();
    if (w == 0) {
        int nw = blockDim.x >> 5;
        float2 r = (threadIdx.x < nw) ? sbuf[threadIdx.x] : make_float2(0.f, 0.f);
        #pragma unroll
        for (int o = 4; o > 0; o >>= 1) {
            r.x += __shfl_xor_sync(0xffffffffu, r.x, o);
            r.y += __shfl_xor_sync(0xffffffffu, r.y, o);
        }
        if (threadIdx.x == 0) sbuf[0] = r;
    }
    __syncthreads();
    return sbuf[0];
}

// ---------------- LN over concat(x, prev_x) feature dim (512) ----------------
__global__ void lnq_kernel(const float* __restrict__ x, const float* __restrict__ px,
                           const float* __restrict__ g, const float* __restrict__ b,
                           float* __restrict__ out) {
    int row = blockIdx.x;          // b*N + n
    int t = threadIdx.x;           // 0..255
    float v0 = x [row * DIMc + t];
    float v1 = px[row * DIMc + t];
    float2 r = blockReduce2(v0 + v1, v0 * v0 + v1 * v1);
    float mean = r.x * (1.0f / 512.0f);
    float var  = r.y * (1.0f / 512.0f) - mean * mean;
    float rstd = rsqrtf(var + 1e-5f);
    out[row * INNERc + t]        = (v0 - mean) * rstd * g[t]        + b[t];
    out[row * INNERc + 256 + t]  = (v1 - mean) * rstd * g[256 + t]  + b[256 + t];
}

// ---------------- LN over kv (256), applying both k and v gamma/beta ----------
__global__ void lnkv_kernel(const float* __restrict__ x, const float* __restrict__ px,
                            const float* __restrict__ gk, const float* __restrict__ bk,
                            const float* __restrict__ gv, const float* __restrict__ bv,
                            float* __restrict__ kout, float* __restrict__ vout) {
    int row = blockIdx.x;          // (s*B + b)*N + n, 0..32767
    int t = threadIdx.x;           // 0..255
    const float* src = (row < Bsz * Nn) ? x : px;
    int r2 = (row < Bsz * Nn) ? row : row - Bsz * Nn;
    float v = src[r2 * DIMc + t];
    float2 r = blockReduce2(v, v * v);
    float mean = r.x * (1.0f / 256.0f);
    float var  = r.y * (1.0f / 256.0f) - mean * mean;
    float rstd = rsqrtf(var + 1e-5f);
    float nrm = (v - mean) * rstd;
    kout[row * DIMc + t] = nrm * gk[t] + bk[t];
    vout[row * DIMc + t] = nrm * gv[t] + bv[t];
}

// ---------------- tiled fp32 SGEMM: C = A(MxK) * B + bias ----------------
// TRANS_B == 0: B is KxN row-major.  TRANS_B == 1: B is NxK row-major (B^T).
template<int TRANS_B, int HAS_BIAS>
__global__ void sgemm_kernel(const float* __restrict__ A, const float* __restrict__ B,
                             const float* __restrict__ bias, float* __restrict__ C,
                             int M, int N, int K) {
    __shared__ float As[16][65];
    __shared__ float Bs[16][64];
    int bm = blockIdx.y * 64, bn = blockIdx.x * 64;
    int t = threadIdx.x;               // 0..255
    int tx = t & 15, ty = t >> 4;
    float acc[4][4] = {};
    for (int k0 = 0; k0 < K; k0 += 16) {
        #pragma unroll
        for (int i = 0; i < 4; i++) {
            int e = t + i * 256;
            int m = e >> 4, k = e & 15;
            As[k][m] = A[(size_t)(bm + m) * K + k0 + k];
        }
        #pragma unroll
        for (int i = 0; i < 4; i++) {
            int e = t + i * 256;
            if (TRANS_B) {
                int n = e >> 4, k = e & 15;
                Bs[k][n] = B[(size_t)(bn + n) * K + k0 + k];
            } else {
                int k = e >> 6, n = e & 63;
                Bs[k][n] = B[(size_t)(k0 + k) * N + bn + n];
            }
        }
        __syncthreads();
        #pragma unroll
        for (int k = 0; k < 16; k++) {
            float a[4], bb[4];
            #pragma unroll
            for (int i = 0; i < 4; i++) a[i]  = As[k][ty * 4 + i];
            #pragma unroll
            for (int j = 0; j < 4; j++) bb[j] = Bs[k][tx * 4 + j];
            #pragma unroll
            for (int i = 0; i < 4; i++)
                #pragma unroll
                for (int j = 0; j < 4; j++)
                    acc[i][j] += a[i] * bb[j];
        }
        __syncthreads();
    }
    #pragma unroll
    for (int i = 0; i < 4; i++)
        #pragma unroll
        for (int j = 0; j < 4; j++) {
            int m = bm + ty * 4 + i, n = bn + tx * 4 + j;
            float v = acc[i][j];
            if (HAS_BIAS) v += bias[n];
            C[(size_t)m * N + n] = v;
        }
}

// ---------------- offsets projection: off = q @ Woff^T + boff ----------------
__global__ void off_kernel(const float* __restrict__ q, const float* __restrict__ Woff,
                           const float* __restrict__ boff, float* __restrict__ off) {
    int idx = blockIdx.x * blockDim.x + threadIdx.x;
    if (idx >= MQ * 16) return;
    int m = idx >> 4, j = idx & 15;
    const float* qr = q + (size_t)m * INNERc;
    const float* wr = Woff + (size_t)j * INNERc;
    float s = 0.f;
    #pragma unroll 8
    for (int k = 0; k < INNERc; k++) s += qr[k] * wr[k];
    off[idx] = s + boff[j];
}

// ---------------- attention: warp per (b,n,h) query, P=2 gather+softmax -------
__global__ void attn_kernel(const float* __restrict__ q, const float* __restrict__ k,
                            const float* __restrict__ v, const float* __restrict__ off,
                            float* __restrict__ ao) {
    int gw = (blockIdx.x * blockDim.x + threadIdx.x) >> 5;   // query index
    int lane = threadIdx.x & 31;
    if (gw >= MQ * Hh) return;
    int bn = gw / Hh;           // b*N + n
    int h  = gw - bn * Hh;
    int b  = bn / Nn;
    int n  = bn - b * Nn;

    float o0 = off[bn * 16 + h * Pp + 0];
    float o1 = off[bn * 16 + h * Pp + 1];
    float t0 = fminf(fmaxf((float)n + o0, 0.f), (float)(2 * Nn - 1));
    float t1 = fminf(fmaxf((float)n + o1, 0.f), (float)(2 * Nn - 1));
    int j0 = (int)t0, j1 = (int)t1;
    int s0 = (j0 >= Nn) ? 1 : 0; int np0 = j0 - s0 * Nn;
    int s1 = (j1 >= Nn) ? 1 : 0; int np1 = j1 - s1 * Nn;

    const float* qb  = q + (size_t)bn * INNERc + h * DHd;
    const float* kb0 = k + ((size_t)(s0 * Bsz + b) * Nn + np0) * INNERc + h * DHd;
    const float* kb1 = k + ((size_t)(s1 * Bsz + b) * Nn + np1) * INNERc + h * DHd;

    float qa = qb[lane], qc = qb[lane + 32];
    float d0 = qa * kb0[lane] + qc * kb0[lane + 32];
    float d1 = qa * kb1[lane] + qc * kb1[lane + 32];
    #pragma unroll
    for (int o = 16; o > 0; o >>= 1) {
        d0 += __shfl_xor_sync(0xffffffffu, d0, o);
        d1 += __shfl_xor_sync(0xffffffffu, d1, o);
    }
    const float scale = 0.125f;   // 64^-0.5
    d0 *= scale; d1 *= scale;
    float mx = fmaxf(d0, d1);
    float e0 = __expf(d0 - mx), e1 = __expf(d1 - mx);
    float inv = 1.0f / (e0 + e1);
    float a0 = e0 * inv, a1 = e1 * inv;

    const float* vb0 = v + ((size_t)(s0 * Bsz + b) * Nn + np0) * INNERc + h * DHd;
    const float* vb1 = v + ((size_t)(s1 * Bsz + b) * Nn + np1) * INNERc + h * DHd;
    float r0 = a0 * vb0[lane]      + a1 * vb1[lane];
    float r1 = a0 * vb0[lane + 32] + a1 * vb1[lane + 32];
    ao[(size_t)bn * INNERc + h * DHd + lane]      = r0;
    ao[(size_t)bn * INNERc + h * DHd + lane + 32] = r1;
}

// ---------------- offsets output: (B,N,H,P) -> (B,H,P,N) ----------------
__global__ void off_out_kernel(const float* __restrict__ off, float* __restrict__ out) {
    int idx = blockIdx.x * blockDim.x + threadIdx.x;
    if (idx >= Bsz * Hh * Pp * Nn) return;
    int n = idx % Nn;
    int r = idx / Nn;
    int p = r % Pp; r /= Pp;
    int h = r % Hh;
    int b = r / Hh;
    out[idx] = off[((size_t)(b * Nn + n)) * 16 + h * Pp + p];
}

// ---------------- launch ----------------
extern "C" void kernel_launch(void* const* d_in, const int* in_sizes, int n_in,
                              void* d_out, int out_size) {
    const float* x     = (const float*)d_in[0];
    const float* px    = (const float*)d_in[1];
    const float* lnqg  = (const float*)d_in[2];
    const float* lnqb  = (const float*)d_in[3];
    const float* lnkg  = (const float*)d_in[4];
    const float* lnkb  = (const float*)d_in[5];
    const float* lnvg  = (const float*)d_in[6];
    const float* lnvb  = (const float*)d_in[7];
    const float* Wq    = (const float*)d_in[8];
    const float* Wk    = (const float*)d_in[9];
    const float* bk    = (const float*)d_in[10];
    const float* Wv    = (const float*)d_in[11];
    const float* bv    = (const float*)d_in[12];
    const float* Woff  = (const float*)d_in[13];
    const float* boff  = (const float*)d_in[14];
    const float* Wout  = (const float*)d_in[15];
    const float* bout  = (const float*)d_in[16];

    float *qln, *qb, *kln, *vln, *kb, *vb, *off, *ao;
    cudaGetSymbolAddress((void**)&qln, g_qln);
    cudaGetSymbolAddress((void**)&qb,  g_q);
    cudaGetSymbolAddress((void**)&kln, g_kln);
    cudaGetSymbolAddress((void**)&vln, g_vln);
    cudaGetSymbolAddress((void**)&kb,  g_k);
    cudaGetSymbolAddress((void**)&vb,  g_v);
    cudaGetSymbolAddress((void**)&off, g_off);
    cudaGetSymbolAddress((void**)&ao,  g_ao);

    float* out_main = (float*)d_out;                 // (B,N,DIM)
    float* out_off  = out_main + (size_t)MQ * DIMc;  // (B,H,P,N)

    lnq_kernel <<<MQ, 256>>>(x, px, lnqg, lnqb, qln);
    lnkv_kernel<<<MKV, 256>>>(x, px, lnkg, lnkb, lnvg, lnvb, kln, vln);

    sgemm_kernel<0,0><<<dim3(INNERc/64, MQ/64),  256>>>(qln, Wq, nullptr, qb, MQ,  INNERc, INNERc);
    sgemm_kernel<0,1><<<dim3(INNERc/64, MKV/64), 256>>>(kln, Wk, bk,      kb, MKV, INNERc, DIMc);
    sgemm_kernel<0,1><<<dim3(INNERc/64, MKV/64), 256>>>(vln, Wv, bv,      vb, MKV, INNERc, DIMc);

    off_kernel<<<(MQ*16 + 255)/256, 256>>>(qb, Woff, boff, off);
    attn_kernel<<<(MQ*Hh)/8, 256>>>(qb, kb, vb, off, ao);
    off_out_kernel<<<(Bsz*Hh*Pp*Nn + 255)/256, 256>>>(off, out_off);

    sgemm_kernel<1,1><<<dim3(DIMc/64, MQ/64), 256>>>(ao, Wout, bout, out_main, MQ, DIMc, INNERc);
}

// round 3
// speedup vs baseline: 1.6252x; 1.6252x over previous
#include <cuda_runtime.h>
#include <cuda_bf16.h>
#include <cstdint>
#include <math.h>

#define Bsz 4
#define Nn 4096
#define DIMc 256
#define Hh 8
#define DHd 64
#define Pp 2
#define INNERc 512
#define MQ (Bsz*Nn)      /* 16384 */
#define MKV (2*Bsz*Nn)   /* 32768 */

// ---------------- scratch (device globals; no allocs allowed) ----------------
__device__ float g_qln[MQ * INNERc];
__device__ float g_q  [MQ * INNERc];
__device__ float g_kln[MKV * DIMc];
__device__ float g_vln[MKV * DIMc];
__device__ float g_k  [MKV * INNERc];
__device__ float g_v  [MKV * INNERc];
__device__ float g_off[MQ * 16];
__device__ float g_ao [MQ * INNERc];
__device__ float g_wqT[INNERc * INNERc];
__device__ float g_wkT[INNERc * DIMc];
__device__ float g_wvT[INNERc * DIMc];

// ================= mma.sync wrappers (compute_103-safe, sm_80+ ISA) =================
__device__ __forceinline__ void mma_tf32(float d[4], const uint32_t a[4], const uint32_t b[2]){
    asm volatile("mma.sync.aligned.m16n8k8.row.col.f32.tf32.tf32.f32 "
        "{%0,%1,%2,%3}, {%4,%5,%6,%7}, {%8,%9}, {%0,%1,%2,%3};"
        : "+f"(d[0]),"+f"(d[1]),"+f"(d[2]),"+f"(d[3])
        : "r"(a[0]),"r"(a[1]),"r"(a[2]),"r"(a[3]),"r"(b[0]),"r"(b[1]));
}
__device__ __forceinline__ void mma_bf16(float d[4], const uint32_t a[4], const uint32_t b[2]){
    asm volatile("mma.sync.aligned.m16n8k16.row.col.f32.bf16.bf16.f32 "
        "{%0,%1,%2,%3}, {%4,%5,%6,%7}, {%8,%9}, {%0,%1,%2,%3};"
        : "+f"(d[0]),"+f"(d[1]),"+f"(d[2]),"+f"(d[3])
        : "r"(a[0]),"r"(a[1]),"r"(a[2]),"r"(a[3]),"r"(b[0]),"r"(b[1]));
}
__device__ __forceinline__ void tf32_split(float v, uint32_t& h, uint32_t& l){
    asm("cvt.rna.tf32.f32 %0, %1;" : "=r"(h) : "f"(v));
    float r = v - __uint_as_float(h);
    asm("cvt.rna.tf32.f32 %0, %1;" : "=r"(l) : "f"(r));
}
__device__ __forceinline__ void bf16_split(float v, uint32_t& h, uint32_t& l){
    __nv_bfloat16 hb = __float2bfloat16(v);
    float r = v - __bfloat162float(hb);
    __nv_bfloat16 lb = __float2bfloat16(r);
    h = (uint32_t)__bfloat16_as_ushort(hb);
    l = (uint32_t)__bfloat16_as_ushort(lb);
}

// ================= tensor-core GEMM with x3 emulation =================
// C[M,Ntot] = A[M,K] @ Bt[Ntot,K]^T (+bias)
// MODE 0: tf32x3 (fp32-grade). MODE 1: bf16x3 (~4e-6 rel).
// 256 threads, tile 128x128, K-chunk 32, fragment-major smem, double buffered.
template<int MODE, int HAS_BIAS>
__global__ void __launch_bounds__(256, 1)
tc_gemm(const float* __restrict__ A, const float* __restrict__ Bt,
        const float* __restrict__ bias, float* __restrict__ C,
        int Ntot, int K)
{
    extern __shared__ uint32_t sm[];
    const int NS   = MODE ? 2 : 4;               // mma k-steps per 32-K chunk
    const int ASZ  = MODE ? 2048 : 4096;         // u32 per A array (8 mt * NS * 32 * 4)
    const int BSZ  = MODE ? 2048 : 4096;         // u32 per B array (16 nt * NS * 32 * 2)
    const int OFF_AH = 0, OFF_AL = ASZ, OFF_BH = 2*ASZ, OFF_BL = 2*ASZ + BSZ;
    const int STG = 2*ASZ + 2*BSZ;

    const int tid = threadIdx.x;
    const int wid = tid >> 5, lane = tid & 31;
    const int wm = wid >> 2, wn = wid & 3;       // warp grid 2x4 -> 64x32 per warp
    const int bm = blockIdx.y * 128, bn = blockIdx.x * 128;

    // writer: each thread owns one half-row of 16 floats per operand
    const int lr = tid >> 1;                     // 0..127 (row of A tile / row of Bt tile)
    const int lc = (tid & 1) * 16;               // k base within chunk
    const float* Ag = A  + (size_t)(bm + lr) * K + lc;
    const float* Bg = Bt + (size_t)(bn + lr) * K + lc;

    const int mt = lr >> 4, rr = lr & 15;
    const int laneA = (rr & 7) * 4, regA = rr >> 3;
    const int nt = lr >> 3, nn = lr & 7;
    const int laneB = nn * 4;

    float4 fa[4], fb[4];

    auto store_stage = [&](int so){
        const float* ra = (const float*)fa;
        const float* rb = (const float*)fb;
        if (MODE == 0){
            #pragma unroll
            for (int j = 0; j < 16; j++){
                int kc = lc + j;
                int ks = kc >> 3;
                uint32_t h, l;
                int ia = ((mt*4 + ks)*32 + laneA + (kc & 3))*4 + regA + 2*((kc >> 2) & 1);
                tf32_split(ra[j], h, l);
                sm[so + OFF_AH + ia] = h; sm[so + OFF_AL + ia] = l;
                int ib = ((nt*4 + ks)*32 + laneB + (kc & 3))*2 + ((kc >> 2) & 1);
                tf32_split(rb[j], h, l);
                sm[so + OFF_BH + ib] = h; sm[so + OFF_BL + ib] = l;
            }
        } else {
            #pragma unroll
            for (int p = 0; p < 8; p++){
                int kc = lc + 2*p;
                int kk = kc & 15, ks16 = kc >> 4;
                uint32_t h0,l0,h1,l1;
                bf16_split(ra[2*p], h0, l0); bf16_split(ra[2*p+1], h1, l1);
                int ia = ((mt*2 + ks16)*32 + laneA + ((kk >> 1) & 3))*4 + regA + 2*(kk >> 3);
                sm[so + OFF_AH + ia] = h0 | (h1 << 16);
                sm[so + OFF_AL + ia] = l0 | (l1 << 16);
                bf16_split(rb[2*p], h0, l0); bf16_split(rb[2*p+1], h1, l1);
                int ib = ((nt*2 + ks16)*32 + laneB + ((kk >> 1) & 3))*2 + (kk >> 3);
                sm[so + OFF_BH + ib] = h0 | (h1 << 16);
                sm[so + OFF_BL + ib] = l0 | (l1 << 16);
            }
        }
    };

    float acc[4][4][4] = {};

    auto compute_stage = [&](int so){
        #pragma unroll
        for (int ks = 0; ks < NS; ks++){
            uint32_t ah[4][4], al_[4][4], bh[4][2], bl[4][2];
            #pragma unroll
            for (int i = 0; i < 4; i++){
                int mg = wm*4 + i;
                int base = so + ((mg*NS + ks)*32 + lane)*4;
                *(uint4*)ah[i]  = *(const uint4*)(sm + base + OFF_AH);
                *(uint4*)al_[i] = *(const uint4*)(sm + base + OFF_AL);
            }
            #pragma unroll
            for (int j = 0; j < 4; j++){
                int ng = wn*4 + j;
                int base = so + ((ng*NS + ks)*32 + lane)*2;
                *(uint2*)bh[j] = *(const uint2*)(sm + base + OFF_BH);
                *(uint2*)bl[j] = *(const uint2*)(sm + base + OFF_BL);
            }
            #pragma unroll
            for (int i = 0; i < 4; i++)
                #pragma unroll
                for (int j = 0; j < 4; j++){
                    if (MODE == 0){
                        mma_tf32(acc[i][j], ah[i],  bh[j]);
                        mma_tf32(acc[i][j], ah[i],  bl[j]);
                        mma_tf32(acc[i][j], al_[i], bh[j]);
                    } else {
                        mma_bf16(acc[i][j], ah[i],  bh[j]);
                        mma_bf16(acc[i][j], ah[i],  bl[j]);
                        mma_bf16(acc[i][j], al_[i], bh[j]);
                    }
                }
        }
    };

    const int NC = K / 32;
    // prologue: chunk 0
    #pragma unroll
    for (int i = 0; i < 4; i++){
        fa[i] = *(const float4*)(Ag + i*4);
        fb[i] = *(const float4*)(Bg + i*4);
    }
    store_stage(0);
    __syncthreads();

    for (int c = 0; c < NC; c++){
        int s = (c & 1) * STG, o = ((c+1) & 1) * STG;
        if (c + 1 < NC){
            const float* Ap = Ag + (c+1)*32;
            const float* Bp = Bg + (c+1)*32;
            #pragma unroll
            for (int i = 0; i < 4; i++){
                fa[i] = *(const float4*)(Ap + i*4);
                fb[i] = *(const float4*)(Bp + i*4);
            }
        }
        compute_stage(s);
        if (c + 1 < NC){
            store_stage(o);
            __syncthreads();
        }
    }

    // epilogue
    #pragma unroll
    for (int i = 0; i < 4; i++){
        int r0 = bm + wm*64 + i*16 + (lane >> 2);
        #pragma unroll
        for (int j = 0; j < 4; j++){
            int c0 = bn + wn*32 + j*8 + (lane & 3)*2;
            float b0 = 0.f, b1 = 0.f;
            if (HAS_BIAS){ b0 = bias[c0]; b1 = bias[c0+1]; }
            float2 v0 = make_float2(acc[i][j][0] + b0, acc[i][j][1] + b1);
            float2 v1 = make_float2(acc[i][j][2] + b0, acc[i][j][3] + b1);
            *(float2*)(C + (size_t)r0 * Ntot + c0)       = v0;
            *(float2*)(C + (size_t)(r0+8) * Ntot + c0)   = v1;
        }
    }
}

#define SMEM_TF32 (2*(4096+4096)*2*4)   /* 131072 B */
#define SMEM_BF16 (2*(2048+2048)*2*4)   /* 65536 B  */

// ================= transpose =================
__global__ void transpose_kernel(const float* __restrict__ in, float* __restrict__ out, int R, int C){
    __shared__ float tile[32][33];
    int c0 = blockIdx.x * 32, r0 = blockIdx.y * 32;
    int tx = threadIdx.x, ty = threadIdx.y;
    #pragma unroll
    for (int i = 0; i < 32; i += 8){
        int r = r0 + ty + i, c = c0 + tx;
        if (r < R && c < C) tile[ty + i][tx] = in[(size_t)r * C + c];
    }
    __syncthreads();
    #pragma unroll
    for (int i = 0; i < 32; i += 8){
        int r = c0 + ty + i, c = r0 + tx;
        if (r < C && c < R) out[(size_t)r * R + c] = tile[tx][ty + i];
    }
}

// ================= block reduce =================
__device__ __forceinline__ float2 blockReduce2(float a, float b) {
    __shared__ float2 sbuf[8];
    #pragma unroll
    for (int o = 16; o > 0; o >>= 1) {
        a += __shfl_xor_sync(0xffffffffu, a, o);
        b += __shfl_xor_sync(0xffffffffu, b, o);
    }
    int w = threadIdx.x >> 5;
    if ((threadIdx.x & 31) == 0) sbuf[w] = make_float2(a, b);
    __syncthreads();
    if (w == 0) {
        int nw = blockDim.x >> 5;
        float2 r = (threadIdx.x < nw) ? sbuf[threadIdx.x] : make_float2(0.f, 0.f);
        #pragma unroll
        for (int o = 4; o > 0; o >>= 1) {
            r.x += __shfl_xor_sync(0xffffffffu, r.x, o);
            r.y += __shfl_xor_sync(0xffffffffu, r.y, o);
        }
        if (threadIdx.x == 0) sbuf[0] = r;
    }
    __syncthreads();
    return sbuf[0];
}

// ================= LayerNorms =================
__global__ void lnq_kernel(const float* __restrict__ x, const float* __restrict__ px,
                           const float* __restrict__ g, const float* __restrict__ b,
                           float* __restrict__ out) {
    int row = blockIdx.x;
    int t = threadIdx.x;
    float v0 = x [row * DIMc + t];
    float v1 = px[row * DIMc + t];
    float2 r = blockReduce2(v0 + v1, v0 * v0 + v1 * v1);
    float mean = r.x * (1.0f / 512.0f);
    float var  = r.y * (1.0f / 512.0f) - mean * mean;
    float rstd = rsqrtf(var + 1e-5f);
    out[row * INNERc + t]       = (v0 - mean) * rstd * g[t]       + b[t];
    out[row * INNERc + 256 + t] = (v1 - mean) * rstd * g[256 + t] + b[256 + t];
}

__global__ void lnkv_kernel(const float* __restrict__ x, const float* __restrict__ px,
                            const float* __restrict__ gk, const float* __restrict__ bk,
                            const float* __restrict__ gv, const float* __restrict__ bv,
                            float* __restrict__ kout, float* __restrict__ vout) {
    int row = blockIdx.x;
    int t = threadIdx.x;
    const float* src = (row < Bsz * Nn) ? x : px;
    int r2 = (row < Bsz * Nn) ? row : row - Bsz * Nn;
    float v = src[r2 * DIMc + t];
    float2 r = blockReduce2(v, v * v);
    float mean = r.x * (1.0f / 256.0f);
    float var  = r.y * (1.0f / 256.0f) - mean * mean;
    float rstd = rsqrtf(var + 1e-5f);
    float nrm = (v - mean) * rstd;
    kout[row * DIMc + t] = nrm * gk[t] + bk[t];
    vout[row * DIMc + t] = nrm * gv[t] + bv[t];
}

// ================= offsets projection (fp32, exact) =================
__global__ void off_kernel(const float* __restrict__ q, const float* __restrict__ Woff,
                           const float* __restrict__ boff, float* __restrict__ off) {
    __shared__ float w[16][INNERc];
    int tid = threadIdx.x;
    for (int i = tid; i < 16 * INNERc; i += 128) w[i >> 9][i & 511] = Woff[i];
    __syncthreads();
    int m = blockIdx.x * 128 + tid;
    const float* qr = q + (size_t)m * INNERc;
    float acc[16];
    #pragma unroll
    for (int j = 0; j < 16; j++) acc[j] = boff[j];
    for (int k0 = 0; k0 < INNERc; k0 += 4){
        float4 qv = *(const float4*)(qr + k0);
        #pragma unroll
        for (int j = 0; j < 16; j++)
            acc[j] += qv.x * w[j][k0] + qv.y * w[j][k0+1] + qv.z * w[j][k0+2] + qv.w * w[j][k0+3];
    }
    #pragma unroll
    for (int j = 0; j < 16; j++) off[(size_t)m * 16 + j] = acc[j];
}

// ================= attention =================
__global__ void attn_kernel(const float* __restrict__ q, const float* __restrict__ k,
                            const float* __restrict__ v, const float* __restrict__ off,
                            float* __restrict__ ao) {
    int gw = (blockIdx.x * blockDim.x + threadIdx.x) >> 5;
    int lane = threadIdx.x & 31;
    if (gw >= MQ * Hh) return;
    int bn = gw / Hh;
    int h  = gw - bn * Hh;
    int b  = bn / Nn;
    int n  = bn - b * Nn;

    float o0 = off[bn * 16 + h * Pp + 0];
    float o1 = off[bn * 16 + h * Pp + 1];
    float t0 = fminf(fmaxf((float)n + o0, 0.f), (float)(2 * Nn - 1));
    float t1 = fminf(fmaxf((float)n + o1, 0.f), (float)(2 * Nn - 1));
    int j0 = (int)t0, j1 = (int)t1;
    int s0 = (j0 >= Nn) ? 1 : 0; int np0 = j0 - s0 * Nn;
    int s1 = (j1 >= Nn) ? 1 : 0; int np1 = j1 - s1 * Nn;

    const float* qb  = q + (size_t)bn * INNERc + h * DHd;
    const float* kb0 = k + ((size_t)(s0 * Bsz + b) * Nn + np0) * INNERc + h * DHd;
    const float* kb1 = k + ((size_t)(s1 * Bsz + b) * Nn + np1) * INNERc + h * DHd;

    float qa = qb[lane], qc = qb[lane + 32];
    float d0 = qa * kb0[lane] + qc * kb0[lane + 32];
    float d1 = qa * kb1[lane] + qc * kb1[lane + 32];
    #pragma unroll
    for (int o = 16; o > 0; o >>= 1) {
        d0 += __shfl_xor_sync(0xffffffffu, d0, o);
        d1 += __shfl_xor_sync(0xffffffffu, d1, o);
    }
    const float scale = 0.125f;
    d0 *= scale; d1 *= scale;
    float mx = fmaxf(d0, d1);
    float e0 = __expf(d0 - mx), e1 = __expf(d1 - mx);
    float inv = 1.0f / (e0 + e1);
    float a0 = e0 * inv, a1 = e1 * inv;

    const float* vb0 = v + ((size_t)(s0 * Bsz + b) * Nn + np0) * INNERc + h * DHd;
    const float* vb1 = v + ((size_t)(s1 * Bsz + b) * Nn + np1) * INNERc + h * DHd;
    float r0 = a0 * vb0[lane]      + a1 * vb1[lane];
    float r1 = a0 * vb0[lane + 32] + a1 * vb1[lane + 32];
    ao[(size_t)bn * INNERc + h * DHd + lane]      = r0;
    ao[(size_t)bn * INNERc + h * DHd + lane + 32] = r1;
}

__global__ void off_out_kernel(const float* __restrict__ off, float* __restrict__ out) {
    int idx = blockIdx.x * blockDim.x + threadIdx.x;
    if (idx >= Bsz * Hh * Pp * Nn) return;
    int n = idx % Nn;
    int r = idx / Nn;
    int p = r % Pp; r /= Pp;
    int h = r % Hh;
    int b = r / Hh;
    out[idx] = off[((size_t)(b * Nn + n)) * 16 + h * Pp + p];
}

// ================= launch =================
extern "C" void kernel_launch(void* const* d_in, const int* in_sizes, int n_in,
                              void* d_out, int out_size) {
    const float* x     = (const float*)d_in[0];
    const float* px    = (const float*)d_in[1];
    const float* lnqg  = (const float*)d_in[2];
    const float* lnqb  = (const float*)d_in[3];
    const float* lnkg  = (const float*)d_in[4];
    const float* lnkb  = (const float*)d_in[5];
    const float* lnvg  = (const float*)d_in[6];
    const float* lnvb  = (const float*)d_in[7];
    const float* Wq    = (const float*)d_in[8];
    const float* Wk    = (const float*)d_in[9];
    const float* bk    = (const float*)d_in[10];
    const float* Wv    = (const float*)d_in[11];
    const float* bv    = (const float*)d_in[12];
    const float* Woff  = (const float*)d_in[13];
    const float* boff  = (const float*)d_in[14];
    const float* Wout  = (const float*)d_in[15];
    const float* bout  = (const float*)d_in[16];

    float *qln, *qb, *kln, *vln, *kb, *vb, *off, *ao, *wqT, *wkT, *wvT;
    cudaGetSymbolAddress((void**)&qln, g_qln);
    cudaGetSymbolAddress((void**)&qb,  g_q);
    cudaGetSymbolAddress((void**)&kln, g_kln);
    cudaGetSymbolAddress((void**)&vln, g_vln);
    cudaGetSymbolAddress((void**)&kb,  g_k);
    cudaGetSymbolAddress((void**)&vb,  g_v);
    cudaGetSymbolAddress((void**)&off, g_off);
    cudaGetSymbolAddress((void**)&ao,  g_ao);
    cudaGetSymbolAddress((void**)&wqT, g_wqT);
    cudaGetSymbolAddress((void**)&wkT, g_wkT);
    cudaGetSymbolAddress((void**)&wvT, g_wvT);

    cudaFuncSetAttribute(tc_gemm<0,0>, cudaFuncAttributeMaxDynamicSharedMemorySize, SMEM_TF32);
    cudaFuncSetAttribute(tc_gemm<1,1>, cudaFuncAttributeMaxDynamicSharedMemorySize, SMEM_BF16);

    float* out_main = (float*)d_out;
    float* out_off  = out_main + (size_t)MQ * DIMc;

    transpose_kernel<<<dim3(INNERc/32, INNERc/32), dim3(32,8)>>>(Wq, wqT, INNERc, INNERc);
    transpose_kernel<<<dim3(INNERc/32, DIMc/32),   dim3(32,8)>>>(Wk, wkT, DIMc, INNERc);
    transpose_kernel<<<dim3(INNERc/32, DIMc/32),   dim3(32,8)>>>(Wv, wvT, DIMc, INNERc);

    lnq_kernel <<<MQ, 256>>>(x, px, lnqg, lnqb, qln);
    lnkv_kernel<<<MKV, 256>>>(x, px, lnkg, lnkb, lnvg, lnvb, kln, vln);

    // q = qln @ Wq  (tf32x3, index-sensitive path)
    tc_gemm<0,0><<<dim3(INNERc/128, MQ/128),  256, SMEM_TF32>>>(qln, wqT, nullptr, qb, INNERc, INNERc);
    // k/v (bf16x3, value-only)
    tc_gemm<1,1><<<dim3(INNERc/128, MKV/128), 256, SMEM_BF16>>>(kln, wkT, bk, kb, INNERc, DIMc);
    tc_gemm<1,1><<<dim3(INNERc/128, MKV/128), 256, SMEM_BF16>>>(vln, wvT, bv, vb, INNERc, DIMc);

    off_kernel<<<MQ/128, 128>>>(qb, Woff, boff, off);
    attn_kernel<<<(MQ*Hh)/8, 256>>>(qb, kb, vb, off, ao);
    off_out_kernel<<<(Bsz*Hh*Pp*Nn + 255)/256, 256>>>(off, out_off);

    // out = ao @ Wout^T + bout (bf16x3)
    tc_gemm<1,1><<<dim3(DIMc/128, MQ/128), 256, SMEM_BF16>>>(ao, Wout, bout, out_main, DIMc, INNERc);
}

// round 4
// speedup vs baseline: 2.4239x; 1.4914x over previous
#include <cuda_runtime.h>
#include <cuda_bf16.h>
#include <cstdint>
#include <math.h>

#define Bsz 4
#define Nn 4096
#define DIMc 256
#define Hh 8
#define DHd 64
#define Pp 2
#define INNERc 512
#define MQ (Bsz*Nn)      /* 16384 */
#define MKV (2*Bsz*Nn)   /* 32768 */

typedef __nv_bfloat16 bf16;

// ---------------- scratch (device globals) ----------------
__device__ bf16  g_qlnh[MQ * INNERc];
__device__ bf16  g_qlnl[MQ * INNERc];
__device__ float g_q   [MQ * INNERc];
__device__ bf16  g_klnh[MKV * DIMc];
__device__ bf16  g_klnl[MKV * DIMc];
__device__ bf16  g_vlnh[MKV * DIMc];
__device__ bf16  g_vlnl[MKV * DIMc];
__device__ float g_k   [MKV * INNERc];
__device__ float g_v   [MKV * INNERc];
__device__ float g_off [MQ * 16];
__device__ bf16  g_aoh [MQ * INNERc];
__device__ bf16  g_aol [MQ * INNERc];
__device__ bf16  g_wqTh[INNERc * INNERc];
__device__ bf16  g_wqTl[INNERc * INNERc];
__device__ bf16  g_wkTh[INNERc * DIMc];
__device__ bf16  g_wkTl[INNERc * DIMc];
__device__ bf16  g_wvTh[INNERc * DIMc];
__device__ bf16  g_wvTl[INNERc * DIMc];
__device__ bf16  g_wouth[DIMc * INNERc];
__device__ bf16  g_woutl[DIMc * INNERc];

// ================= helpers =================
__device__ __forceinline__ uint32_t smem_u32(const void* p){
    uint32_t a;
    asm("{ .reg .u64 t; cvta.to.shared.u64 t, %1; cvt.u32.u64 %0, t; }" : "=r"(a) : "l"(p));
    return a;
}
__device__ __forceinline__ void bsplit(float v, bf16& h, bf16& l){
    h = __float2bfloat16(v);
    l = __float2bfloat16(v - __bfloat162float(h));
}
__device__ __forceinline__ void mma_bf16(float d[4], const uint32_t a[4], const uint32_t b[2]){
    asm volatile("mma.sync.aligned.m16n8k16.row.col.f32.bf16.bf16.f32 "
        "{%0,%1,%2,%3}, {%4,%5,%6,%7}, {%8,%9}, {%0,%1,%2,%3};"
        : "+f"(d[0]),"+f"(d[1]),"+f"(d[2]),"+f"(d[3])
        : "r"(a[0]),"r"(a[1]),"r"(a[2]),"r"(a[3]),"r"(b[0]),"r"(b[1]));
}
__device__ __forceinline__ void ldsm4(uint32_t r[4], uint32_t addr){
    asm volatile("ldmatrix.sync.aligned.m8n8.x4.shared.b16 {%0,%1,%2,%3}, [%4];"
        : "=r"(r[0]),"=r"(r[1]),"=r"(r[2]),"=r"(r[3]) : "r"(addr));
}
__device__ __forceinline__ void cp16(uint32_t dst, const void* src){
    asm volatile("cp.async.cg.shared.global [%0], [%1], 16;" :: "r"(dst), "l"(src));
}

// ================= bf16x3 tensor-core GEMM =================
// C[M,Ntot] = (Ah+Al)[M,K] @ (Bh+Bl)[Ntot,K]^T (+bias), x3 terms.
// 256 thr, tile 128x128, K-chunk 32, 3-stage cp.async, ldmatrix fragments.
// smem per stage: 4 planes x (128 rows x 80B) = 40960B. Total 122880B.
#define TILE_B 10240
#define STAGE_B 40960
#define GEMM_SMEM (3*STAGE_B)

template<int HAS_BIAS>
__global__ void __launch_bounds__(256, 1)
bf16x3_gemm(const bf16* __restrict__ Ah, const bf16* __restrict__ Al,
            const bf16* __restrict__ Bh, const bf16* __restrict__ Bl,
            const float* __restrict__ bias, float* __restrict__ C,
            int Ntot, int K)
{
    extern __shared__ char smem[];
    const uint32_t sb = smem_u32(smem);
    const int tid = threadIdx.x, lane = tid & 31, wid = tid >> 5;
    const int wm = wid >> 2, wn = wid & 3;         // 2x4 warp grid, 64x32 per warp
    const int bm = blockIdx.y * 128, bn = blockIdx.x * 128;
    const int NC = K >> 5;

    const int lr  = tid >> 2;       // 0..63
    const int lcc = tid & 3;        // chunk within row (16B each)

    auto load_stage = [&](int buf, int kc){
        uint32_t sbase = sb + buf * STAGE_B + lr * 80 + lcc * 16;
        size_t ao = (size_t)(bm + lr) * K + kc + lcc * 8;
        size_t bo = (size_t)(bn + lr) * K + kc + lcc * 8;
        size_t row64 = (size_t)64 * K;
        cp16(sbase,                        Ah + ao);
        cp16(sbase + 64*80,                Ah + ao + row64);
        cp16(sbase + TILE_B,               Al + ao);
        cp16(sbase + TILE_B + 64*80,       Al + ao + row64);
        cp16(sbase + 2*TILE_B,             Bh + bo);
        cp16(sbase + 2*TILE_B + 64*80,     Bh + bo + row64);
        cp16(sbase + 3*TILE_B,             Bl + bo);
        cp16(sbase + 3*TILE_B + 64*80,     Bl + bo + row64);
        asm volatile("cp.async.commit_group;" ::: "memory");
    };

    float acc[4][4][4] = {};
    const uint32_t arow = (uint32_t)(lane & 15) * 80 + (uint32_t)(lane >> 4) * 16;

    auto compute = [&](int buf){
        uint32_t base = sb + buf * STAGE_B;
        #pragma unroll
        for (int ks = 0; ks < 2; ks++){
            uint32_t ah[4][4], al_[4][4], bh[4][2], bl[4][2];
            #pragma unroll
            for (int i = 0; i < 4; i++){
                uint32_t a = base + (uint32_t)(wm*64 + i*16) * 80 + arow + ks*32;
                ldsm4(ah[i],  a);
                ldsm4(al_[i], a + TILE_B);
            }
            #pragma unroll
            for (int jp = 0; jp < 2; jp++){
                uint32_t a = base + 2*TILE_B + (uint32_t)(wn*32 + jp*16) * 80 + arow + ks*32;
                uint32_t r4[4];
                ldsm4(r4, a);
                bh[jp*2][0]=r4[0]; bh[jp*2+1][0]=r4[1]; bh[jp*2][1]=r4[2]; bh[jp*2+1][1]=r4[3];
                ldsm4(r4, a + TILE_B);
                bl[jp*2][0]=r4[0]; bl[jp*2+1][0]=r4[1]; bl[jp*2][1]=r4[2]; bl[jp*2+1][1]=r4[3];
            }
            #pragma unroll
            for (int i = 0; i < 4; i++)
                #pragma unroll
                for (int j = 0; j < 4; j++){
                    mma_bf16(acc[i][j], ah[i],  bh[j]);
                    mma_bf16(acc[i][j], ah[i],  bl[j]);
                    mma_bf16(acc[i][j], al_[i], bh[j]);
                }
        }
    };

    load_stage(0, 0);
    load_stage(1, 32);
    load_stage(2, 64);

    for (int c = 0; c < NC; c++){
        if (c <= NC - 3)      asm volatile("cp.async.wait_group 2;" ::: "memory");
        else if (c == NC - 2) asm volatile("cp.async.wait_group 1;" ::: "memory");
        else                  asm volatile("cp.async.wait_group 0;" ::: "memory");
        __syncthreads();
        compute(c % 3);
        __syncthreads();
        if (c + 3 < NC) load_stage(c % 3, (c + 3) * 32);
    }

    #pragma unroll
    for (int i = 0; i < 4; i++){
        int r0 = bm + wm*64 + i*16 + (lane >> 2);
        #pragma unroll
        for (int j = 0; j < 4; j++){
            int c0 = bn + wn*32 + j*8 + (lane & 3)*2;
            float b0 = 0.f, b1 = 0.f;
            if (HAS_BIAS){ b0 = bias[c0]; b1 = bias[c0+1]; }
            *(float2*)(C + (size_t)r0 * Ntot + c0)     = make_float2(acc[i][j][0]+b0, acc[i][j][1]+b1);
            *(float2*)(C + (size_t)(r0+8) * Ntot + c0) = make_float2(acc[i][j][2]+b0, acc[i][j][3]+b1);
        }
    }
}

// ================= transpose + split: out[C,R] planes = split(in[R,C]^T) =====
__global__ void transpose_split(const float* __restrict__ in,
                                bf16* __restrict__ oh, bf16* __restrict__ ol,
                                int R, int C){
    __shared__ float tile[32][33];
    int c0 = blockIdx.x * 32, r0 = blockIdx.y * 32;
    int tx = threadIdx.x, ty = threadIdx.y;
    #pragma unroll
    for (int i = 0; i < 32; i += 8)
        tile[ty + i][tx] = in[(size_t)(r0 + ty + i) * C + c0 + tx];
    __syncthreads();
    #pragma unroll
    for (int i = 0; i < 32; i += 8){
        float v = tile[tx][ty + i];
        bf16 h, l; bsplit(v, h, l);
        size_t o = (size_t)(c0 + ty + i) * R + r0 + tx;
        oh[o] = h; ol[o] = l;
    }
}

// ================= elementwise split (Wout) =================
__global__ void split_kernel(const float* __restrict__ in,
                             bf16* __restrict__ oh, bf16* __restrict__ ol, int n){
    int i = blockIdx.x * blockDim.x + threadIdx.x;
    if (i >= n) return;
    bf16 h, l; bsplit(in[i], h, l);
    oh[i] = h; ol[i] = l;
}

// ================= block reduce =================
__device__ __forceinline__ float2 blockReduce2(float a, float b) {
    __shared__ float2 sbuf[8];
    #pragma unroll
    for (int o = 16; o > 0; o >>= 1) {
        a += __shfl_xor_sync(0xffffffffu, a, o);
        b += __shfl_xor_sync(0xffffffffu, b, o);
    }
    int w = threadIdx.x >> 5;
    if ((threadIdx.x & 31) == 0) sbuf[w] = make_float2(a, b);
    __syncthreads();
    if (w == 0) {
        int nw = blockDim.x >> 5;
        float2 r = (threadIdx.x < nw) ? sbuf[threadIdx.x] : make_float2(0.f, 0.f);
        #pragma unroll
        for (int o = 4; o > 0; o >>= 1) {
            r.x += __shfl_xor_sync(0xffffffffu, r.x, o);
            r.y += __shfl_xor_sync(0xffffffffu, r.y, o);
        }
        if (threadIdx.x == 0) sbuf[0] = r;
    }
    __syncthreads();
    return sbuf[0];
}

// ================= LayerNorms (emit bf16 hi/lo planes) =================
__global__ void lnq_kernel(const float* __restrict__ x, const float* __restrict__ px,
                           const float* __restrict__ g, const float* __restrict__ b,
                           bf16* __restrict__ oh, bf16* __restrict__ ol) {
    int row = blockIdx.x;
    int t = threadIdx.x;
    float v0 = x [row * DIMc + t];
    float v1 = px[row * DIMc + t];
    float2 r = blockReduce2(v0 + v1, v0 * v0 + v1 * v1);
    float mean = r.x * (1.0f / 512.0f);
    float var  = r.y * (1.0f / 512.0f) - mean * mean;
    float rstd = rsqrtf(var + 1e-5f);
    float y0 = (v0 - mean) * rstd * g[t]       + b[t];
    float y1 = (v1 - mean) * rstd * g[256 + t] + b[256 + t];
    bf16 h, l;
    bsplit(y0, h, l); oh[row * INNERc + t] = h;       ol[row * INNERc + t] = l;
    bsplit(y1, h, l); oh[row * INNERc + 256 + t] = h; ol[row * INNERc + 256 + t] = l;
}

__global__ void lnkv_kernel(const float* __restrict__ x, const float* __restrict__ px,
                            const float* __restrict__ gk, const float* __restrict__ bk,
                            const float* __restrict__ gv, const float* __restrict__ bv,
                            bf16* __restrict__ kh, bf16* __restrict__ kl,
                            bf16* __restrict__ vh, bf16* __restrict__ vl) {
    int row = blockIdx.x;
    int t = threadIdx.x;
    const float* src = (row < Bsz * Nn) ? x : px;
    int r2 = (row < Bsz * Nn) ? row : row - Bsz * Nn;
    float v = src[r2 * DIMc + t];
    float2 r = blockReduce2(v, v * v);
    float mean = r.x * (1.0f / 256.0f);
    float var  = r.y * (1.0f / 256.0f) - mean * mean;
    float rstd = rsqrtf(var + 1e-5f);
    float nrm = (v - mean) * rstd;
    bf16 h, l;
    bsplit(nrm * gk[t] + bk[t], h, l); kh[row * DIMc + t] = h; kl[row * DIMc + t] = l;
    bsplit(nrm * gv[t] + bv[t], h, l); vh[row * DIMc + t] = h; vl[row * DIMc + t] = l;
}

// ================= offsets projection (fp32) + fused transposed output ========
__global__ void off_kernel(const float* __restrict__ q, const float* __restrict__ Woff,
                           const float* __restrict__ boff, float* __restrict__ off,
                           float* __restrict__ off_out) {
    __shared__ float w[16][INNERc];
    int tid = threadIdx.x;
    for (int i = tid; i < 16 * INNERc; i += 128) w[i >> 9][i & 511] = Woff[i];
    __syncthreads();
    int m = blockIdx.x * 128 + tid;        // b*N + n
    const float* qr = q + (size_t)m * INNERc;
    float acc[16];
    #pragma unroll
    for (int j = 0; j < 16; j++) acc[j] = boff[j];
    for (int k0 = 0; k0 < INNERc; k0 += 4){
        float4 qv = *(const float4*)(qr + k0);
        #pragma unroll
        for (int j = 0; j < 16; j++)
            acc[j] += qv.x * w[j][k0] + qv.y * w[j][k0+1] + qv.z * w[j][k0+2] + qv.w * w[j][k0+3];
    }
    int b = m >> 12, n = m & 4095;
    #pragma unroll
    for (int j = 0; j < 16; j++){
        off[(size_t)m * 16 + j] = acc[j];
        // out layout (B,H,P,N): j = h*2+p
        off_out[((size_t)(b * 16 + j)) * Nn + n] = acc[j];
    }
}

// ================= attention (emits bf16 hi/lo planes) =================
__global__ void attn_kernel(const float* __restrict__ q, const float* __restrict__ k,
                            const float* __restrict__ v, const float* __restrict__ off,
                            bf16* __restrict__ aoh, bf16* __restrict__ aol) {
    int gw = (blockIdx.x * blockDim.x + threadIdx.x) >> 5;
    int lane = threadIdx.x & 31;
    if (gw >= MQ * Hh) return;
    int bn = gw / Hh;
    int h  = gw - bn * Hh;
    int b  = bn / Nn;
    int n  = bn - b * Nn;

    float o0 = off[bn * 16 + h * Pp + 0];
    float o1 = off[bn * 16 + h * Pp + 1];
    float t0 = fminf(fmaxf((float)n + o0, 0.f), (float)(2 * Nn - 1));
    float t1 = fminf(fmaxf((float)n + o1, 0.f), (float)(2 * Nn - 1));
    int j0 = (int)t0, j1 = (int)t1;
    int s0 = (j0 >= Nn) ? 1 : 0; int np0 = j0 - s0 * Nn;
    int s1 = (j1 >= Nn) ? 1 : 0; int np1 = j1 - s1 * Nn;

    const float* qb  = q + (size_t)bn * INNERc + h * DHd;
    const float* kb0 = k + ((size_t)(s0 * Bsz + b) * Nn + np0) * INNERc + h * DHd;
    const float* kb1 = k + ((size_t)(s1 * Bsz + b) * Nn + np1) * INNERc + h * DHd;

    float qa = qb[lane], qc = qb[lane + 32];
    float d0 = qa * kb0[lane] + qc * kb0[lane + 32];
    float d1 = qa * kb1[lane] + qc * kb1[lane + 32];
    #pragma unroll
    for (int o = 16; o > 0; o >>= 1) {
        d0 += __shfl_xor_sync(0xffffffffu, d0, o);
        d1 += __shfl_xor_sync(0xffffffffu, d1, o);
    }
    const float scale = 0.125f;
    d0 *= scale; d1 *= scale;
    float mx = fmaxf(d0, d1);
    float e0 = __expf(d0 - mx), e1 = __expf(d1 - mx);
    float inv = 1.0f / (e0 + e1);
    float a0 = e0 * inv, a1 = e1 * inv;

    const float* vb0 = v + ((size_t)(s0 * Bsz + b) * Nn + np0) * INNERc + h * DHd;
    const float* vb1 = v + ((size_t)(s1 * Bsz + b) * Nn + np1) * INNERc + h * DHd;
    float r0 = a0 * vb0[lane]      + a1 * vb1[lane];
    float r1 = a0 * vb0[lane + 32] + a1 * vb1[lane + 32];
    bf16 hh, ll;
    size_t o_base = (size_t)bn * INNERc + h * DHd;
    bsplit(r0, hh, ll); aoh[o_base + lane]      = hh; aol[o_base + lane]      = ll;
    bsplit(r1, hh, ll); aoh[o_base + lane + 32] = hh; aol[o_base + lane + 32] = ll;
}

// ================= launch =================
extern "C" void kernel_launch(void* const* d_in, const int* in_sizes, int n_in,
                              void* d_out, int out_size) {
    const float* x     = (const float*)d_in[0];
    const float* px    = (const float*)d_in[1];
    const float* lnqg  = (const float*)d_in[2];
    const float* lnqb  = (const float*)d_in[3];
    const float* lnkg  = (const float*)d_in[4];
    const float* lnkb  = (const float*)d_in[5];
    const float* lnvg  = (const float*)d_in[6];
    const float* lnvb  = (const float*)d_in[7];
    const float* Wq    = (const float*)d_in[8];
    const float* Wk    = (const float*)d_in[9];
    const float* bk    = (const float*)d_in[10];
    const float* Wv    = (const float*)d_in[11];
    const float* bv    = (const float*)d_in[12];
    const float* Woff  = (const float*)d_in[13];
    const float* boff  = (const float*)d_in[14];
    const float* Wout  = (const float*)d_in[15];
    const float* bout  = (const float*)d_in[16];

    bf16 *qlnh,*qlnl,*klnh,*klnl,*vlnh,*vlnl,*aoh,*aol;
    bf16 *wqTh,*wqTl,*wkTh,*wkTl,*wvTh,*wvTl,*wouth,*woutl;
    float *qb,*kb,*vb,*off;
    cudaGetSymbolAddress((void**)&qlnh, g_qlnh);
    cudaGetSymbolAddress((void**)&qlnl, g_qlnl);
    cudaGetSymbolAddress((void**)&qb,   g_q);
    cudaGetSymbolAddress((void**)&klnh, g_klnh);
    cudaGetSymbolAddress((void**)&klnl, g_klnl);
    cudaGetSymbolAddress((void**)&vlnh, g_vlnh);
    cudaGetSymbolAddress((void**)&vlnl, g_vlnl);
    cudaGetSymbolAddress((void**)&kb,   g_k);
    cudaGetSymbolAddress((void**)&vb,   g_v);
    cudaGetSymbolAddress((void**)&off,  g_off);
    cudaGetSymbolAddress((void**)&aoh,  g_aoh);
    cudaGetSymbolAddress((void**)&aol,  g_aol);
    cudaGetSymbolAddress((void**)&wqTh, g_wqTh);
    cudaGetSymbolAddress((void**)&wqTl, g_wqTl);
    cudaGetSymbolAddress((void**)&wkTh, g_wkTh);
    cudaGetSymbolAddress((void**)&wkTl, g_wkTl);
    cudaGetSymbolAddress((void**)&wvTh, g_wvTh);
    cudaGetSymbolAddress((void**)&wvTl, g_wvTl);
    cudaGetSymbolAddress((void**)&wouth, g_wouth);
    cudaGetSymbolAddress((void**)&woutl, g_woutl);

    cudaFuncSetAttribute(bf16x3_gemm<0>, cudaFuncAttributeMaxDynamicSharedMemorySize, GEMM_SMEM);
    cudaFuncSetAttribute(bf16x3_gemm<1>, cudaFuncAttributeMaxDynamicSharedMemorySize, GEMM_SMEM);

    float* out_main = (float*)d_out;
    float* out_off  = out_main + (size_t)MQ * DIMc;

    // weight prep: transpose+split to [N,K] bf16 planes; Wout split only
    transpose_split<<<dim3(INNERc/32, INNERc/32), dim3(32,8)>>>(Wq, wqTh, wqTl, INNERc, INNERc);
    transpose_split<<<dim3(INNERc/32, DIMc/32),   dim3(32,8)>>>(Wk, wkTh, wkTl, DIMc, INNERc);
    transpose_split<<<dim3(INNERc/32, DIMc/32),   dim3(32,8)>>>(Wv, wvTh, wvTl, DIMc, INNERc);
    split_kernel<<<(DIMc*INNERc + 255)/256, 256>>>(Wout, wouth, woutl, DIMc*INNERc);

    lnq_kernel <<<MQ, 256>>>(x, px, lnqg, lnqb, qlnh, qlnl);
    lnkv_kernel<<<MKV, 256>>>(x, px, lnkg, lnkb, lnvg, lnvb, klnh, klnl, vlnh, vlnl);

    // q = qln @ Wq
    bf16x3_gemm<0><<<dim3(INNERc/128, MQ/128),  256, GEMM_SMEM>>>(qlnh, qlnl, wqTh, wqTl, nullptr, qb, INNERc, INNERc);
    // k = kln @ Wk + bk ; v = vln @ Wv + bv
    bf16x3_gemm<1><<<dim3(INNERc/128, MKV/128), 256, GEMM_SMEM>>>(klnh, klnl, wkTh, wkTl, bk, kb, INNERc, DIMc);
    bf16x3_gemm<1><<<dim3(INNERc/128, MKV/128), 256, GEMM_SMEM>>>(vlnh, vlnl, wvTh, wvTl, bv, vb, INNERc, DIMc);

    off_kernel<<<MQ/128, 128>>>(qb, Woff, boff, off, out_off);
    attn_kernel<<<(MQ*Hh)/8, 256>>>(qb, kb, vb, off, aoh, aol);

    // out = ao @ Wout^T + bout
    bf16x3_gemm<1><<<dim3(DIMc/128, MQ/128), 256, GEMM_SMEM>>>(aoh, aol, wouth, woutl, bout, out_main, DIMc, INNERc);
}